// round 13
// baseline (speedup 1.0000x reference)
#include <cuda_runtime.h>
#include <math.h>
#include <stdint.h>

#define DM   512
#define NH   8
#define DH   64
#define BAT  2
#define SEQ  2048
#define NTOK (BAT*SEQ)   // 4096

// Scratch (device globals)
__device__ float g_x[NTOK*DM];           // x pre-rounded to tf32
__device__ float g_w[4*DM*DM];           // Wq,Wk,Wv,Wo pre-rounded to tf32
__device__ float g_q[BAT*NH*SEQ*DH];     // [B,H,S,d], pre-scaled by 1/8, tf32
__device__ float g_k[BAT*NH*SEQ*DH];     // [B,H,S,d], tf32
__device__ float g_vt[BAT*NH*DH*SEQ];    // V TRANSPOSED [B,H,d,S], tf32
__device__ float g_att[NTOK*DM];         // attention output [B,S,D], tf32

// ---------------------------------------------------------------------------
// helpers
// ---------------------------------------------------------------------------
__device__ __forceinline__ unsigned f2tf(float f) {
    unsigned u;
    asm("cvt.rna.tf32.f32 %0, %1;" : "=r"(u) : "f"(f));
    return u;
}
__device__ __forceinline__ float rtf(float f) { return __uint_as_float(f2tf(f)); }

__device__ __forceinline__ void mma8(float* c, const unsigned* a, const unsigned* b) {
    asm volatile(
        "mma.sync.aligned.m16n8k8.row.col.f32.tf32.tf32.f32 "
        "{%0,%1,%2,%3}, {%4,%5,%6,%7}, {%8,%9}, {%0,%1,%2,%3};"
        : "+f"(c[0]), "+f"(c[1]), "+f"(c[2]), "+f"(c[3])
        : "r"(a[0]), "r"(a[1]), "r"(a[2]), "r"(a[3]), "r"(b[0]), "r"(b[1]));
}

__device__ __forceinline__ void ldsm4(unsigned* r, uint32_t addr) {
    asm volatile("ldmatrix.sync.aligned.m8n8.x4.shared.b16 {%0,%1,%2,%3}, [%4];"
        : "=r"(r[0]), "=r"(r[1]), "=r"(r[2]), "=r"(r[3]) : "r"(addr));
}

#define CPA(dst, src) \
    asm volatile("cp.async.cg.shared.global [%0], [%1], 16;" :: "r"(dst), "l"(src))
#define CPC() asm volatile("cp.async.commit_group;" ::: "memory")
#define CPW(n) asm volatile("cp.async.wait_group %0;" :: "n"(n) : "memory")

#define BAR_SYNC(id, cnt) \
    asm volatile("bar.sync %0, %1;" :: "n"(id), "n"(cnt) : "memory")
#define BAR_SYNC_R(id, cnt) \
    asm volatile("bar.sync %0, %1;" :: "r"(id), "n"(cnt) : "memory")
#define BAR_ARRIVE_R(id, cnt) \
    asm volatile("bar.arrive %0, %1;" :: "r"(id), "n"(cnt) : "memory")

// ---------------------------------------------------------------------------
// prep: RNA-round fp32 -> tf32 for x (y=0) and W[0..3] (y=1..4), one launch
// ---------------------------------------------------------------------------
__global__ __launch_bounds__(256)
void prep_all(const float* __restrict__ x,
              const float* __restrict__ w0, const float* __restrict__ w1,
              const float* __restrict__ w2, const float* __restrict__ w3,
              float* __restrict__ xr, float* __restrict__ wrd,
              int xn4, int wn4)
{
    const int y = blockIdx.y;
    const int i = blockIdx.x * 256 + threadIdx.x;
    const float* src;
    float* dst;
    int n4;
    if (y == 0) { src = x; dst = xr; n4 = xn4; }
    else {
        src = (y == 1) ? w0 : (y == 2) ? w1 : (y == 3) ? w2 : w3;
        dst = wrd + (size_t)(y - 1) * DM * DM;
        n4 = wn4;
    }
    if (i < n4) {
        float4 v = ((const float4*)src)[i];
        v.x = rtf(v.x); v.y = rtf(v.y); v.z = rtf(v.z); v.w = rtf(v.w);
        ((float4*)dst)[i] = v;
    }
}

// ---------------------------------------------------------------------------
// Fused QKV projection, 3-STAGE cp.async pipeline.
// CTA tile 128x128, grid (12, 32); 8 warps (4x2), warp tile 32x64, K-chunk 32.
// ---------------------------------------------------------------------------
#define PBM 128
#define PBK 32
#define PLD 36
#define TLD 132
#define QKV_BUFW ((PBM + 128) * PLD)        // 9216 words per stage
#define QKV_SMEM (3 * QKV_BUFW * 4)         // 110592 B (2 CTAs/SM)
#define NCHUNK (DM / PBK)                   // 16

__global__ __launch_bounds__(256, 2)
void qkv_mma(const float* __restrict__ A, const float* __restrict__ W4,
             const float* __restrict__ bq, const float* __restrict__ bk,
             const float* __restrict__ bv,
             float* __restrict__ outq, float* __restrict__ outk,
             float* __restrict__ outvt)
{
    extern __shared__ unsigned psm[];

    const int tid  = threadIdx.x;
    const int lane = tid & 31;
    const int wid  = tid >> 5;
    const int wr   = wid >> 1;
    const int wc   = wid & 1;
    const int g    = lane >> 2;
    const int t4   = lane & 3;
    const int bm   = blockIdx.y;
    const int bnG  = blockIdx.x;
    const int mat  = bnG >> 2;
    const int nb   = bnG & 3;

    const float* Ag = A + (size_t)bm * PBM * DM;
    const float* Wg = W4 + (size_t)mat * DM * DM + (size_t)nb * 128 * DM;
    const float* bias = (mat == 0) ? bq : (mat == 1) ? bk : bv;

    const uint32_t sb   = (uint32_t)__cvta_generic_to_shared(psm);
    const uint32_t BUFB = QKV_BUFW * 4;
    const uint32_t bOff = PBM * PLD * 4;

    const int lr7 = lane & 7, lb3 = (lane >> 3) & 1, lb4 = (lane >> 4) & 1;
    uint32_t aAddr[2], bAddr[4];
#pragma unroll
    for (int i = 0; i < 2; i++)
        aAddr[i] = sb + ((wr*32 + i*16 + lr7 + lb3*8) * PLD + lb4*4) * 4;
#pragma unroll
    for (int jj = 0; jj < 4; jj++)
        bAddr[jj] = sb + bOff + ((wc*64 + jj*16 + lr7 + lb4*8) * PLD + lb3*4) * 4;

    const int cr = tid >> 3, cq = tid & 7;

    // prologue: chunks 0,1 -> bufs 0,1 (two commit groups)
#pragma unroll
    for (int p = 0; p < 2; p++) {
        const uint32_t pb = p * BUFB;
        const int k0 = p * PBK;
#pragma unroll
        for (int i = 0; i < 4; i++) {
            const int r = cr + i * 32;
            CPA(sb + pb + (r*PLD + cq*4)*4, Ag + (size_t)r * DM + k0 + cq*4);
            CPA(sb + pb + bOff + (r*PLD + cq*4)*4, Wg + (size_t)r * DM + k0 + cq*4);
        }
        CPC();
    }

    float acc[2][8][4];
#pragma unroll
    for (int i = 0; i < 2; i++)
#pragma unroll
        for (int j = 0; j < 8; j++)
#pragma unroll
            for (int r = 0; r < 4; r++) acc[i][j][r] = 0.f;

    int buf = 0;
    for (int c = 0; c < NCHUNK; c++) {
        const uint32_t cu = buf * BUFB;
        if (c < NCHUNK - 2) { CPW(1); } else { CPW(0); }
        __syncthreads();        // all warps done with chunk c-1 -> its buf free
        if (c + 2 < NCHUNK) {
            const int nbf = (buf + 2 >= 3) ? buf - 1 : buf + 2;
            const uint32_t nb_ = nbf * BUFB;
            const int k0 = (c + 2) * PBK;
#pragma unroll
            for (int i = 0; i < 4; i++) {
                const int r = cr + i * 32;
                CPA(sb + nb_ + (r*PLD + cq*4)*4, Ag + (size_t)r * DM + k0 + cq*4);
                CPA(sb + nb_ + bOff + (r*PLD + cq*4)*4, Wg + (size_t)r * DM + k0 + cq*4);
            }
            CPC();
        }
#pragma unroll
        for (int kk = 0; kk < PBK / 8; kk++) {
            unsigned af[2][4], bf[4][4];
            ldsm4(af[0], aAddr[0] + cu + kk * 32);
            ldsm4(af[1], aAddr[1] + cu + kk * 32);
#pragma unroll
            for (int jj = 0; jj < 4; jj++)
                ldsm4(bf[jj], bAddr[jj] + cu + kk * 32);
#pragma unroll
            for (int i = 0; i < 2; i++)
#pragma unroll
                for (int j = 0; j < 8; j++)
                    mma8(acc[i][j], af[i], bf[j >> 1] + (j & 1) * 2);
        }
        buf = (buf + 1 == 3) ? 0 : buf + 1;
    }

    if (mat == 2) {
        float* Ts = (float*)psm;
        __syncthreads();
#pragma unroll
        for (int i = 0; i < 2; i++) {
            const int ss = wr*32 + i*16 + g;
#pragma unroll
            for (int j = 0; j < 8; j++) {
                const int cc = wc*64 + j*8 + 2*t4;
                const float b0 = bias[nb*128 + cc], b1 = bias[nb*128 + cc + 1];
                Ts[cc * TLD + ss]           = rtf(acc[i][j][0] + b0);
                Ts[(cc + 1) * TLD + ss]     = rtf(acc[i][j][1] + b1);
                Ts[cc * TLD + ss + 8]       = rtf(acc[i][j][2] + b0);
                Ts[(cc + 1) * TLD + ss + 8] = rtf(acc[i][j][3] + b1);
            }
        }
        __syncthreads();
        const int bb = bm >> 4;
        const int sbase = (bm & 15) * 128;
#pragma unroll
        for (int t = 0; t < 16; t++) {
            const int idx = tid + t * 256;
            const int cc = idx >> 5;
            const int sl = (idx & 31) * 4;
            const int mc = nb * 128 + cc;
            const int hh = mc >> 6, dd = mc & (DH - 1);
            float4 val = *(float4*)&Ts[cc * TLD + sl];
            *(float4*)(outvt + (((size_t)bb * NH + hh) * DH + dd) * SEQ + sbase + sl) = val;
        }
        return;
    }

    float* out = mat ? outk : outq;
    const float scale = mat ? 1.0f : 0.125f;
#pragma unroll
    for (int i = 0; i < 2; i++) {
        const int row0 = bm * PBM + wr * 32 + i * 16 + g;
        const int row1 = row0 + 8;
        const int b0 = row0 >> 11, s0 = row0 & (SEQ - 1);
        const int b1 = row1 >> 11, s1 = row1 & (SEQ - 1);
#pragma unroll
        for (int j = 0; j < 8; j++) {
            const int col0 = nb * 128 + wc * 64 + j * 8 + 2 * t4;
            const int hh = col0 >> 6, cc = col0 & (DH - 1);
            float* p0 = &out[(((size_t)b0 * NH + hh) * SEQ + s0) * DH + cc];
            p0[0] = rtf((acc[i][j][0] + bias[col0])     * scale);
            p0[1] = rtf((acc[i][j][1] + bias[col0 + 1]) * scale);
            float* p1 = &out[(((size_t)b1 * NH + hh) * SEQ + s1) * DH + cc];
            p1[0] = rtf((acc[i][j][2] + bias[col0])     * scale);
            p1[1] = rtf((acc[i][j][3] + bias[col0 + 1]) * scale);
        }
    }
}

// ---------------------------------------------------------------------------
// O projection, 3-STAGE cp.async pipeline. CTA tile 128x64, grid (8, 32).
// ---------------------------------------------------------------------------
#define O_BUFW ((PBM + 64) * PLD)           // 6912 words per stage
#define O_SMEM (3 * O_BUFW * 4)             // 82944 B (2 CTAs/SM)

__global__ __launch_bounds__(256, 2)
void o_mma(const float* __restrict__ A, const float* __restrict__ W,
           const float* __restrict__ bias, float* __restrict__ out)
{
    extern __shared__ unsigned psm[];

    const int tid  = threadIdx.x;
    const int lane = tid & 31;
    const int wid  = tid >> 5;
    const int wr   = wid >> 1;
    const int wc   = wid & 1;
    const int g    = lane >> 2;
    const int t4   = lane & 3;
    const int bm   = blockIdx.y;
    const int bn   = blockIdx.x;

    const float* Ag = A + (size_t)bm * PBM * DM;
    const float* Wg = W + (size_t)bn * 64 * DM;

    const uint32_t sb   = (uint32_t)__cvta_generic_to_shared(psm);
    const uint32_t BUFB = O_BUFW * 4;
    const uint32_t bOff = PBM * PLD * 4;

    const int lr7 = lane & 7, lb3 = (lane >> 3) & 1, lb4 = (lane >> 4) & 1;
    uint32_t aAddr[2], bAddr[2];
#pragma unroll
    for (int i = 0; i < 2; i++)
        aAddr[i] = sb + ((wr*32 + i*16 + lr7 + lb3*8) * PLD + lb4*4) * 4;
#pragma unroll
    for (int jj = 0; jj < 2; jj++)
        bAddr[jj] = sb + bOff + ((wc*32 + jj*16 + lr7 + lb4*8) * PLD + lb3*4) * 4;

    const int cr = tid >> 3, cq = tid & 7;

    // prologue: chunks 0,1
#pragma unroll
    for (int p = 0; p < 2; p++) {
        const uint32_t pb = p * BUFB;
        const int k0 = p * PBK;
#pragma unroll
        for (int i = 0; i < 4; i++) {
            const int r = cr + i * 32;
            CPA(sb + pb + (r*PLD + cq*4)*4, Ag + (size_t)r * DM + k0 + cq*4);
        }
#pragma unroll
        for (int i = 0; i < 2; i++) {
            const int r = cr + i * 32;
            CPA(sb + pb + bOff + (r*PLD + cq*4)*4, Wg + (size_t)r * DM + k0 + cq*4);
        }
        CPC();
    }

    float acc[2][4][4];
#pragma unroll
    for (int i = 0; i < 2; i++)
#pragma unroll
        for (int j = 0; j < 4; j++)
#pragma unroll
            for (int r = 0; r < 4; r++) acc[i][j][r] = 0.f;

    int buf = 0;
    for (int c = 0; c < NCHUNK; c++) {
        const uint32_t cu = buf * BUFB;
        if (c < NCHUNK - 2) { CPW(1); } else { CPW(0); }
        __syncthreads();
        if (c + 2 < NCHUNK) {
            const int nbf = (buf + 2 >= 3) ? buf - 1 : buf + 2;
            const uint32_t nb_ = nbf * BUFB;
            const int k0 = (c + 2) * PBK;
#pragma unroll
            for (int i = 0; i < 4; i++) {
                const int r = cr + i * 32;
                CPA(sb + nb_ + (r*PLD + cq*4)*4, Ag + (size_t)r * DM + k0 + cq*4);
            }
#pragma unroll
            for (int i = 0; i < 2; i++) {
                const int r = cr + i * 32;
                CPA(sb + nb_ + bOff + (r*PLD + cq*4)*4, Wg + (size_t)r * DM + k0 + cq*4);
            }
            CPC();
        }
#pragma unroll
        for (int kk = 0; kk < PBK / 8; kk++) {
            unsigned af[2][4], bf[2][4];
            ldsm4(af[0], aAddr[0] + cu + kk * 32);
            ldsm4(af[1], aAddr[1] + cu + kk * 32);
            ldsm4(bf[0], bAddr[0] + cu + kk * 32);
            ldsm4(bf[1], bAddr[1] + cu + kk * 32);
#pragma unroll
            for (int i = 0; i < 2; i++) {
                mma8(acc[i][0], af[i], bf[0]);
                mma8(acc[i][1], af[i], bf[0] + 2);
                mma8(acc[i][2], af[i], bf[1]);
                mma8(acc[i][3], af[i], bf[1] + 2);
            }
        }
        buf = (buf + 1 == 3) ? 0 : buf + 1;
    }

#pragma unroll
    for (int i = 0; i < 2; i++) {
        const int row0 = bm * PBM + wr * 32 + i * 16 + g;
        const int row1 = row0 + 8;
#pragma unroll
        for (int j = 0; j < 4; j++) {
            const int col0 = bn * 64 + wc * 32 + j * 8 + 2 * t4;
            float* p0 = &out[(size_t)row0 * DM + col0];
            p0[0] = acc[i][j][0] + bias[col0];
            p0[1] = acc[i][j][1] + bias[col0 + 1];
            float* p1 = &out[(size_t)row1 * DM + col0];
            p1[0] = acc[i][j][2] + bias[col0];
            p1[1] = acc[i][j][3] + bias[col0 + 1];
        }
    }
}

// ---------------------------------------------------------------------------
// Flash attention (unchanged from R12): warp-specialized, pairwise P handoff.
// ---------------------------------------------------------------------------
#define ALD 68
#define KVSTRIDE (2 * 64 * ALD * 4)
#define PS_OFF   (2 * KVSTRIDE)
#define L_OFF    (PS_OFF + 128 * ALD * 4)
#define ATT_SMEM_BYTES (L_OFF + 512)

__global__ __launch_bounds__(256, 2)
void attn_mma(const float* __restrict__ Q, const float* __restrict__ K,
              const float* __restrict__ VT, float* __restrict__ out)
{
    extern __shared__ unsigned sm[];

    const int tid  = threadIdx.x;
    const int lane = tid & 31;
    const int wid  = tid >> 5;
    const bool isS = wid < 4;
    const int wg   = wid & 3;
    const int wrow = wg * 32;
    const int g    = lane >> 2;
    const int t4   = lane & 3;
    const int qt   = blockIdx.x;
    const int h    = blockIdx.y;
    const int b    = blockIdx.z;

    const int idReady = 1 + wg;
    const int idFree  = 5 + wg;

    const float* Qg = Q  + (((size_t)b * NH + h) * SEQ + qt * 128) * DH;
    const float* Kg = K  + ((size_t)b * NH + h) * SEQ * DH;
    const float* Vg = VT + ((size_t)b * NH + h) * DH * SEQ;

    const uint32_t sb  = (uint32_t)__cvta_generic_to_shared(sm);
    const uint32_t psB = sb + PS_OFF;
    float* l_smem = (float*)((char*)sm + L_OFF);

    const int lr7 = lane & 7, lb3 = (lane >> 3) & 1, lb4 = (lane >> 4) & 1;
    const uint32_t bK0 = sb + ((lr7 + lb4 * 8) * ALD + lb3 * 4) * 4;
    const uint32_t bV0 = bK0 + 64 * ALD * 4;
    uint32_t aP0[2];
#pragma unroll
    for (int i = 0; i < 2; i++)
        aP0[i] = psB + ((wrow + i * 16 + lr7 + lb3 * 8) * ALD + lb4 * 4) * 4;

    const int wg_tid = tid & 127;
    const int r8  = wg_tid >> 4, q16 = wg_tid & 15;

    {
        const int rq = tid >> 4, qq = tid & 15;
#pragma unroll
        for (int i = 0; i < 8; i++) {
            const int rr = rq + i * 16;
            CPA(psB + (rr * ALD + qq * 4) * 4, Qg + rr * DH + qq * 4);
        }
        CPC();
    }
    if (isS) {
#pragma unroll
        for (int i = 0; i < 8; i++) {
            const int rr = r8 + i * 8;
            CPA(sb + (rr * ALD + q16 * 4) * 4, Kg + rr * DH + q16 * 4);
        }
        CPC();
    } else {
#pragma unroll
        for (int i = 0; i < 8; i++) {
            const int rr = r8 + i * 8;
            CPA(sb + 64 * ALD * 4 + (rr * ALD + q16 * 4) * 4,
                Vg + (size_t)rr * SEQ + q16 * 4);
        }
        CPC();
    }
    CPW(1);
    __syncthreads();

    if (isS) {
        unsigned Qf[2][8][4];
#pragma unroll
        for (int i = 0; i < 2; i++)
#pragma unroll
            for (int kk = 0; kk < 8; kk++) ldsm4(Qf[i][kk], aP0[i] + kk * 32);

        float lA[2] = {0.f, 0.f}, lB[2] = {0.f, 0.f};
        unsigned* Ps = sm + PS_OFF / 4;

        for (int kt = 0; kt < SEQ / 64; kt++) {
            const uint32_t cu = (uint32_t)(kt & 1) * KVSTRIDE;
            CPW(0);
            BAR_SYNC(9, 128);
            if (kt < SEQ / 64 - 1) {
                const uint32_t nb = (uint32_t)((kt + 1) & 1) * KVSTRIDE;
                const float* Kt = Kg + (size_t)(kt + 1) * 64 * DH;
#pragma unroll
                for (int i = 0; i < 8; i++) {
                    const int rr = r8 + i * 8;
                    CPA(sb + nb + (rr * ALD + q16 * 4) * 4, Kt + rr * DH + q16 * 4);
                }
                CPC();
            }

#pragma unroll
            for (int hf = 0; hf < 2; hf++) {
                float s[2][4][4];
#pragma unroll
                for (int i = 0; i < 2; i++)
#pragma unroll
                    for (int j = 0; j < 4; j++)
#pragma unroll
                        for (int r = 0; r < 4; r++) s[i][j][r] = 0.f;
#pragma unroll
                for (int kk = 0; kk < 8; kk++) {
#pragma unroll
                    for (int jl = 0; jl < 2; jl++) {
                        unsigned bk[4];
                        ldsm4(bk, bK0 + cu + (2*hf + jl) * (16 * ALD * 4) + kk * 32);
#pragma unroll
                        for (int i = 0; i < 2; i++) {
                            mma8(s[i][2*jl],     Qf[i][kk], bk);
                            mma8(s[i][2*jl + 1], Qf[i][kk], bk + 2);
                        }
                    }
                }
#pragma unroll
                for (int i = 0; i < 2; i++)
#pragma unroll
                    for (int j = 0; j < 4; j++) {
                        s[i][j][0] = __expf(s[i][j][0]);
                        s[i][j][1] = __expf(s[i][j][1]);
                        s[i][j][2] = __expf(s[i][j][2]);
                        s[i][j][3] = __expf(s[i][j][3]);
                        lA[i] += s[i][j][0] + s[i][j][1];
                        lB[i] += s[i][j][2] + s[i][j][3];
                    }
                if (hf == 0) BAR_SYNC_R(idFree, 64);
#pragma unroll
                for (int i = 0; i < 2; i++)
#pragma unroll
                    for (int j = 0; j < 4; j++) {
                        const int col = (4*hf + j) * 8 + 2 * t4;
                        uint2 u0, u1;
                        u0.x = f2tf(s[i][j][0]); u0.y = f2tf(s[i][j][1]);
                        u1.x = f2tf(s[i][j][2]); u1.y = f2tf(s[i][j][3]);
                        *(uint2*)&Ps[(wrow + i*16 + g)     * ALD + col] = u0;
                        *(uint2*)&Ps[(wrow + i*16 + g + 8) * ALD + col] = u1;
                    }
            }
            BAR_ARRIVE_R(idReady, 64);
        }

#pragma unroll
        for (int i = 0; i < 2; i++) {
            lA[i] += __shfl_xor_sync(0xffffffffu, lA[i], 1);
            lA[i] += __shfl_xor_sync(0xffffffffu, lA[i], 2);
            lB[i] += __shfl_xor_sync(0xffffffffu, lB[i], 1);
            lB[i] += __shfl_xor_sync(0xffffffffu, lB[i], 2);
            if (t4 == 0) {
                l_smem[wrow + i*16 + g]     = lA[i];
                l_smem[wrow + i*16 + g + 8] = lB[i];
            }
        }
        __syncthreads();
    } else {
        float o[2][8][4];
#pragma unroll
        for (int i = 0; i < 2; i++)
#pragma unroll
            for (int j = 0; j < 8; j++)
#pragma unroll
                for (int r = 0; r < 4; r++) o[i][j][r] = 0.f;

        BAR_ARRIVE_R(idFree, 64);

        for (int kt = 0; kt < SEQ / 64; kt++) {
            const uint32_t cu = (uint32_t)(kt & 1) * KVSTRIDE;
            CPW(0);
            BAR_SYNC(10, 128);
            if (kt < SEQ / 64 - 1) {
                const uint32_t nb = (uint32_t)((kt + 1) & 1) * KVSTRIDE;
                const float* Vt = Vg + (kt + 1) * 64;
#pragma unroll
                for (int i = 0; i < 8; i++) {
                    const int rr = r8 + i * 8;
                    CPA(sb + nb + 64 * ALD * 4 + (rr * ALD + q16 * 4) * 4,
                        Vt + (size_t)rr * SEQ + q16 * 4);
                }
                CPC();
            }
            BAR_SYNC_R(idReady, 64);

#pragma unroll
            for (int kc = 0; kc < 8; kc++) {
                unsigned ap[2][4];
                ldsm4(ap[0], aP0[0] + kc * 32);
                ldsm4(ap[1], aP0[1] + kc * 32);
#pragma unroll
                for (int jj = 0; jj < 4; jj++) {
                    unsigned bv[4];
                    ldsm4(bv, bV0 + cu + jj * (16 * ALD * 4) + kc * 32);
#pragma unroll
                    for (int i = 0; i < 2; i++) {
                        mma8(o[i][2 * jj],     ap[i], bv);
                        mma8(o[i][2 * jj + 1], ap[i], bv + 2);
                    }
                }
            }
            BAR_ARRIVE_R(idFree, 64);
        }

        __syncthreads();

#pragma unroll
        for (int i = 0; i < 2; i++) {
            const float invA = 1.f / l_smem[wrow + i*16 + g];
            const float invB = 1.f / l_smem[wrow + i*16 + g + 8];
            const int rA = qt * 128 + wrow + i * 16 + g;
            float* oA = out + ((size_t)(b * SEQ + rA)) * DM + h * DH;
            float* oB = oA + (size_t)8 * DM;
#pragma unroll
            for (int j = 0; j < 8; j++) {
                const int col = j * 8 + 2 * t4;
                float2 vA, vB;
                vA.x = rtf(o[i][j][0] * invA); vA.y = rtf(o[i][j][1] * invA);
                vB.x = rtf(o[i][j][2] * invB); vB.y = rtf(o[i][j][3] * invB);
                *(float2*)(oA + col) = vA;
                *(float2*)(oB + col) = vB;
            }
        }
    }
}

// ---------------------------------------------------------------------------
extern "C" void kernel_launch(void* const* d_in, const int* in_sizes, int n_in,
                              void* d_out, int out_size)
{
    const float* x  = (const float*)d_in[0];
    const float* Wq = (const float*)d_in[1];
    const float* bq = (const float*)d_in[2];
    const float* Wk = (const float*)d_in[3];
    const float* bk = (const float*)d_in[4];
    const float* Wv = (const float*)d_in[5];
    const float* bv = (const float*)d_in[6];
    const float* Wo = (const float*)d_in[7];
    const float* bo = (const float*)d_in[8];
    float* out = (float*)d_out;

    float *xr, *wr_, *q, *k, *vt, *att;
    cudaGetSymbolAddress((void**)&xr,  g_x);
    cudaGetSymbolAddress((void**)&wr_, g_w);
    cudaGetSymbolAddress((void**)&q,   g_q);
    cudaGetSymbolAddress((void**)&k,   g_k);
    cudaGetSymbolAddress((void**)&vt,  g_vt);
    cudaGetSymbolAddress((void**)&att, g_att);

    cudaFuncSetAttribute(qkv_mma,
        cudaFuncAttributeMaxDynamicSharedMemorySize, QKV_SMEM);
    cudaFuncSetAttribute(o_mma,
        cudaFuncAttributeMaxDynamicSharedMemorySize, O_SMEM);
    cudaFuncSetAttribute(attn_mma,
        cudaFuncAttributeMaxDynamicSharedMemorySize, ATT_SMEM_BYTES);

    const int XN4 = NTOK * DM / 4;
    const int WN4 = DM * DM / 4;

    prep_all<<<dim3(XN4 / 256, 5), 256>>>(x, Wq, Wk, Wv, Wo, xr, wr_, XN4, WN4);

    qkv_mma<<<dim3(12, NTOK / PBM), 256, QKV_SMEM>>>(
        xr, wr_, bq, bk, bv, q, k, vt);

    attn_mma<<<dim3(SEQ / 128, NH, BAT), 256, ATT_SMEM_BYTES>>>(q, k, vt, att);

    o_mma<<<dim3(8, NTOK / PBM), 256, O_SMEM>>>(att, wr_ + 3*DM*DM, bo, out);
}

// round 15
// speedup vs baseline: 1.0233x; 1.0233x over previous
#include <cuda_runtime.h>
#include <math.h>
#include <stdint.h>

#define DM   512
#define NH   8
#define DH   64
#define BAT  2
#define SEQ  2048
#define NTOK (BAT*SEQ)   // 4096

// Scratch (device globals)
__device__ float g_x[NTOK*DM];           // x pre-rounded to tf32
__device__ float g_w[4*DM*DM];           // Wq,Wk,Wv,Wo pre-rounded to tf32
__device__ float g_q[BAT*NH*SEQ*DH];     // [B,H,S,d], scaled by log2(e)/8, tf32
__device__ float g_k[BAT*NH*SEQ*DH];     // [B,H,S,d], tf32
__device__ float g_vt[BAT*NH*DH*SEQ];    // V TRANSPOSED [B,H,d,S], tf32
__device__ float g_att[NTOK*DM];         // attention output [B,S,D], tf32

// ---------------------------------------------------------------------------
// helpers
// ---------------------------------------------------------------------------
__device__ __forceinline__ unsigned f2tf(float f) {
    unsigned u;
    asm("cvt.rna.tf32.f32 %0, %1;" : "=r"(u) : "f"(f));
    return u;
}
__device__ __forceinline__ float rtf(float f) { return __uint_as_float(f2tf(f)); }
__device__ __forceinline__ float ex2(float f) {
    float r;
    asm("ex2.approx.f32 %0, %1;" : "=f"(r) : "f"(f));
    return r;
}

__device__ __forceinline__ void mma8(float* c, const unsigned* a, const unsigned* b) {
    asm volatile(
        "mma.sync.aligned.m16n8k8.row.col.f32.tf32.tf32.f32 "
        "{%0,%1,%2,%3}, {%4,%5,%6,%7}, {%8,%9}, {%0,%1,%2,%3};"
        : "+f"(c[0]), "+f"(c[1]), "+f"(c[2]), "+f"(c[3])
        : "r"(a[0]), "r"(a[1]), "r"(a[2]), "r"(a[3]), "r"(b[0]), "r"(b[1]));
}

__device__ __forceinline__ void ldsm4(unsigned* r, uint32_t addr) {
    asm volatile("ldmatrix.sync.aligned.m8n8.x4.shared.b16 {%0,%1,%2,%3}, [%4];"
        : "=r"(r[0]), "=r"(r[1]), "=r"(r[2]), "=r"(r[3]) : "r"(addr));
}

#define CPA(dst, src) \
    asm volatile("cp.async.cg.shared.global [%0], [%1], 16;" :: "r"(dst), "l"(src))
#define CPC() asm volatile("cp.async.commit_group;" ::: "memory")
#define CPW(n) asm volatile("cp.async.wait_group %0;" :: "n"(n) : "memory")

#define BAR_SYNC(id, cnt) \
    asm volatile("bar.sync %0, %1;" :: "n"(id), "n"(cnt) : "memory")
#define BAR_SYNC_R(id, cnt) \
    asm volatile("bar.sync %0, %1;" :: "r"(id), "n"(cnt) : "memory")
#define BAR_ARRIVE_R(id, cnt) \
    asm volatile("bar.arrive %0, %1;" :: "r"(id), "n"(cnt) : "memory")

// ---------------------------------------------------------------------------
// prep: RNA-round fp32 -> tf32 for x (y=0) and W[0..3] (y=1..4), one launch
// ---------------------------------------------------------------------------
__global__ __launch_bounds__(256)
void prep_all(const float* __restrict__ x,
              const float* __restrict__ w0, const float* __restrict__ w1,
              const float* __restrict__ w2, const float* __restrict__ w3,
              float* __restrict__ xr, float* __restrict__ wrd,
              int xn4, int wn4)
{
    const int y = blockIdx.y;
    const int i = blockIdx.x * 256 + threadIdx.x;
    const float* src;
    float* dst;
    int n4;
    if (y == 0) { src = x; dst = xr; n4 = xn4; }
    else {
        src = (y == 1) ? w0 : (y == 2) ? w1 : (y == 3) ? w2 : w3;
        dst = wrd + (size_t)(y - 1) * DM * DM;
        n4 = wn4;
    }
    if (i < n4) {
        float4 v = ((const float4*)src)[i];
        v.x = rtf(v.x); v.y = rtf(v.y); v.z = rtf(v.z); v.w = rtf(v.w);
        ((float4*)dst)[i] = v;
    }
}

// ---------------------------------------------------------------------------
// Fused QKV projection (inputs pre-rounded tf32):
// CTA tile 128x128, grid (12, 32); 8 warps (4x2), warp tile 32x64, K-chunk 32,
// cp.async double-buffer. Q epilogue scale = log2(e)/8 (for ex2 softmax).
// ---------------------------------------------------------------------------
#define PBM 128
#define PBK 32
#define PLD 36
#define TLD 132
#define QKV_BUFW ((PBM + 128) * PLD)
#define QKV_SMEM (2 * QKV_BUFW * 4)
#define QSCALE 0.18033688011112042f   // log2(e) / 8

__global__ __launch_bounds__(256, 2)
void qkv_mma(const float* __restrict__ A, const float* __restrict__ W4,
             const float* __restrict__ bq, const float* __restrict__ bk,
             const float* __restrict__ bv,
             float* __restrict__ outq, float* __restrict__ outk,
             float* __restrict__ outvt)
{
    extern __shared__ unsigned psm[];

    const int tid  = threadIdx.x;
    const int lane = tid & 31;
    const int wid  = tid >> 5;
    const int wr   = wid >> 1;
    const int wc   = wid & 1;
    const int g    = lane >> 2;
    const int t4   = lane & 3;
    const int bm   = blockIdx.y;
    const int bnG  = blockIdx.x;
    const int mat  = bnG >> 2;
    const int nb   = bnG & 3;

    const float* Ag = A + (size_t)bm * PBM * DM;
    const float* Wg = W4 + (size_t)mat * DM * DM + (size_t)nb * 128 * DM;
    const float* bias = (mat == 0) ? bq : (mat == 1) ? bk : bv;

    const uint32_t sb   = (uint32_t)__cvta_generic_to_shared(psm);
    const uint32_t BUFB = QKV_BUFW * 4;
    const uint32_t bOff = PBM * PLD * 4;

    const int lr7 = lane & 7, lb3 = (lane >> 3) & 1, lb4 = (lane >> 4) & 1;
    uint32_t aAddr[2], bAddr[4];
#pragma unroll
    for (int i = 0; i < 2; i++)
        aAddr[i] = sb + ((wr*32 + i*16 + lr7 + lb3*8) * PLD + lb4*4) * 4;
#pragma unroll
    for (int jj = 0; jj < 4; jj++)
        bAddr[jj] = sb + bOff + ((wc*64 + jj*16 + lr7 + lb4*8) * PLD + lb3*4) * 4;

    const int cr = tid >> 3, cq = tid & 7;

#pragma unroll
    for (int i = 0; i < 4; i++) {
        const int r = cr + i * 32;
        CPA(sb + (r*PLD + cq*4)*4, Ag + (size_t)r * DM + cq*4);
        CPA(sb + bOff + (r*PLD + cq*4)*4, Wg + (size_t)r * DM + cq*4);
    }
    CPC();

    float acc[2][8][4];
#pragma unroll
    for (int i = 0; i < 2; i++)
#pragma unroll
        for (int j = 0; j < 8; j++)
#pragma unroll
            for (int r = 0; r < 4; r++) acc[i][j][r] = 0.f;

    for (int c = 0; c < DM / PBK; c++) {
        const uint32_t cu = (c & 1) * BUFB;
        CPW(0);
        __syncthreads();
        if (c < DM / PBK - 1) {
            const uint32_t nbuf = ((c + 1) & 1) * BUFB;
            const int k0 = (c + 1) * PBK;
#pragma unroll
            for (int i = 0; i < 4; i++) {
                const int r = cr + i * 32;
                CPA(sb + nbuf + (r*PLD + cq*4)*4, Ag + (size_t)r * DM + k0 + cq*4);
                CPA(sb + nbuf + bOff + (r*PLD + cq*4)*4, Wg + (size_t)r * DM + k0 + cq*4);
            }
            CPC();
        }
#pragma unroll
        for (int kk = 0; kk < PBK / 8; kk++) {
            unsigned af[2][4], bf[4][4];
            ldsm4(af[0], aAddr[0] + cu + kk * 32);
            ldsm4(af[1], aAddr[1] + cu + kk * 32);
#pragma unroll
            for (int jj = 0; jj < 4; jj++)
                ldsm4(bf[jj], bAddr[jj] + cu + kk * 32);
#pragma unroll
            for (int i = 0; i < 2; i++)
#pragma unroll
                for (int j = 0; j < 8; j++)
                    mma8(acc[i][j], af[i], bf[j >> 1] + (j & 1) * 2);
        }
    }

    if (mat == 2) {
        float* Ts = (float*)psm;
        __syncthreads();
#pragma unroll
        for (int i = 0; i < 2; i++) {
            const int ss = wr*32 + i*16 + g;
#pragma unroll
            for (int j = 0; j < 8; j++) {
                const int cc = wc*64 + j*8 + 2*t4;
                const float b0 = bias[nb*128 + cc], b1 = bias[nb*128 + cc + 1];
                Ts[cc * TLD + ss]           = rtf(acc[i][j][0] + b0);
                Ts[(cc + 1) * TLD + ss]     = rtf(acc[i][j][1] + b1);
                Ts[cc * TLD + ss + 8]       = rtf(acc[i][j][2] + b0);
                Ts[(cc + 1) * TLD + ss + 8] = rtf(acc[i][j][3] + b1);
            }
        }
        __syncthreads();
        const int bb = bm >> 4;
        const int sbase = (bm & 15) * 128;
#pragma unroll
        for (int t = 0; t < 16; t++) {
            const int idx = tid + t * 256;
            const int cc = idx >> 5;
            const int sl = (idx & 31) * 4;
            const int mc = nb * 128 + cc;
            const int hh = mc >> 6, dd = mc & (DH - 1);
            float4 val = *(float4*)&Ts[cc * TLD + sl];
            *(float4*)(outvt + (((size_t)bb * NH + hh) * DH + dd) * SEQ + sbase + sl) = val;
        }
        return;
    }

    float* out = mat ? outk : outq;
    const float scale = mat ? 1.0f : QSCALE;
#pragma unroll
    for (int i = 0; i < 2; i++) {
        const int row0 = bm * PBM + wr * 32 + i * 16 + g;
        const int row1 = row0 + 8;
        const int b0 = row0 >> 11, s0 = row0 & (SEQ - 1);
        const int b1 = row1 >> 11, s1 = row1 & (SEQ - 1);
#pragma unroll
        for (int j = 0; j < 8; j++) {
            const int col0 = nb * 128 + wc * 64 + j * 8 + 2 * t4;
            const int hh = col0 >> 6, cc = col0 & (DH - 1);
            float* p0 = &out[(((size_t)b0 * NH + hh) * SEQ + s0) * DH + cc];
            p0[0] = rtf((acc[i][j][0] + bias[col0])     * scale);
            p0[1] = rtf((acc[i][j][1] + bias[col0 + 1]) * scale);
            float* p1 = &out[(((size_t)b1 * NH + hh) * SEQ + s1) * DH + cc];
            p1[0] = rtf((acc[i][j][2] + bias[col0])     * scale);
            p1[1] = rtf((acc[i][j][3] + bias[col0 + 1]) * scale);
        }
    }
}

// ---------------------------------------------------------------------------
// O projection (R12 version): CTA tile 128x64, grid (8, 32), 2-stage pipeline.
// ---------------------------------------------------------------------------
#define O_BUFW ((PBM + 64) * PLD)
#define O_SMEM (2 * O_BUFW * 4)

__global__ __launch_bounds__(256, 2)
void o_mma(const float* __restrict__ A, const float* __restrict__ W,
           const float* __restrict__ bias, float* __restrict__ out)
{
    extern __shared__ unsigned psm[];

    const int tid  = threadIdx.x;
    const int lane = tid & 31;
    const int wid  = tid >> 5;
    const int wr   = wid >> 1;
    const int wc   = wid & 1;
    const int g    = lane >> 2;
    const int t4   = lane & 3;
    const int bm   = blockIdx.y;
    const int bn   = blockIdx.x;

    const float* Ag = A + (size_t)bm * PBM * DM;
    const float* Wg = W + (size_t)bn * 64 * DM;

    const uint32_t sb   = (uint32_t)__cvta_generic_to_shared(psm);
    const uint32_t BUFB = O_BUFW * 4;
    const uint32_t bOff = PBM * PLD * 4;

    const int lr7 = lane & 7, lb3 = (lane >> 3) & 1, lb4 = (lane >> 4) & 1;
    uint32_t aAddr[2], bAddr[2];
#pragma unroll
    for (int i = 0; i < 2; i++)
        aAddr[i] = sb + ((wr*32 + i*16 + lr7 + lb3*8) * PLD + lb4*4) * 4;
#pragma unroll
    for (int jj = 0; jj < 2; jj++)
        bAddr[jj] = sb + bOff + ((wc*32 + jj*16 + lr7 + lb4*8) * PLD + lb3*4) * 4;

    const int cr = tid >> 3, cq = tid & 7;

#pragma unroll
    for (int i = 0; i < 4; i++) {
        const int r = cr + i * 32;
        CPA(sb + (r*PLD + cq*4)*4, Ag + (size_t)r * DM + cq*4);
    }
#pragma unroll
    for (int i = 0; i < 2; i++) {
        const int r = cr + i * 32;
        CPA(sb + bOff + (r*PLD + cq*4)*4, Wg + (size_t)r * DM + cq*4);
    }
    CPC();

    float acc[2][4][4];
#pragma unroll
    for (int i = 0; i < 2; i++)
#pragma unroll
        for (int j = 0; j < 4; j++)
#pragma unroll
            for (int r = 0; r < 4; r++) acc[i][j][r] = 0.f;

    for (int c = 0; c < DM / PBK; c++) {
        const uint32_t cu = (c & 1) * BUFB;
        CPW(0);
        __syncthreads();
        if (c < DM / PBK - 1) {
            const uint32_t nbuf = ((c + 1) & 1) * BUFB;
            const int k0 = (c + 1) * PBK;
#pragma unroll
            for (int i = 0; i < 4; i++) {
                const int r = cr + i * 32;
                CPA(sb + nbuf + (r*PLD + cq*4)*4, Ag + (size_t)r * DM + k0 + cq*4);
            }
#pragma unroll
            for (int i = 0; i < 2; i++) {
                const int r = cr + i * 32;
                CPA(sb + nbuf + bOff + (r*PLD + cq*4)*4, Wg + (size_t)r * DM + k0 + cq*4);
            }
            CPC();
        }
#pragma unroll
        for (int kk = 0; kk < PBK / 8; kk++) {
            unsigned af[2][4], bf[2][4];
            ldsm4(af[0], aAddr[0] + cu + kk * 32);
            ldsm4(af[1], aAddr[1] + cu + kk * 32);
            ldsm4(bf[0], bAddr[0] + cu + kk * 32);
            ldsm4(bf[1], bAddr[1] + cu + kk * 32);
#pragma unroll
            for (int i = 0; i < 2; i++) {
                mma8(acc[i][0], af[i], bf[0]);
                mma8(acc[i][1], af[i], bf[0] + 2);
                mma8(acc[i][2], af[i], bf[1]);
                mma8(acc[i][3], af[i], bf[1] + 2);
            }
        }
    }

#pragma unroll
    for (int i = 0; i < 2; i++) {
        const int row0 = bm * PBM + wr * 32 + i * 16 + g;
        const int row1 = row0 + 8;
#pragma unroll
        for (int j = 0; j < 4; j++) {
            const int col0 = bn * 64 + wc * 32 + j * 8 + 2 * t4;
            float* p0 = &out[(size_t)row0 * DM + col0];
            p0[0] = acc[i][j][0] + bias[col0];
            p0[1] = acc[i][j][1] + bias[col0 + 1];
            float* p1 = &out[(size_t)row1 * DM + col0];
            p1[0] = acc[i][j][2] + bias[col0];
            p1[1] = acc[i][j][3] + bias[col0 + 1];
        }
    }
}

// ---------------------------------------------------------------------------
// Flash attention (R12 structure): warp-specialized, pairwise P handoff.
// Q pre-scaled by log2(e)/8 -> softmax numerator via raw ex2 (no FMUL).
// ---------------------------------------------------------------------------
#define ALD 68
#define KVSTRIDE (2 * 64 * ALD * 4)
#define PS_OFF   (2 * KVSTRIDE)
#define L_OFF    (PS_OFF + 128 * ALD * 4)
#define ATT_SMEM_BYTES (L_OFF + 512)

__global__ __launch_bounds__(256, 2)
void attn_mma(const float* __restrict__ Q, const float* __restrict__ K,
              const float* __restrict__ VT, float* __restrict__ out)
{
    extern __shared__ unsigned sm[];

    const int tid  = threadIdx.x;
    const int lane = tid & 31;
    const int wid  = tid >> 5;
    const bool isS = wid < 4;
    const int wg   = wid & 3;
    const int wrow = wg * 32;
    const int g    = lane >> 2;
    const int t4   = lane & 3;
    const int qt   = blockIdx.x;
    const int h    = blockIdx.y;
    const int b    = blockIdx.z;

    const int idReady = 1 + wg;
    const int idFree  = 5 + wg;

    const float* Qg = Q  + (((size_t)b * NH + h) * SEQ + qt * 128) * DH;
    const float* Kg = K  + ((size_t)b * NH + h) * SEQ * DH;
    const float* Vg = VT + ((size_t)b * NH + h) * DH * SEQ;

    const uint32_t sb  = (uint32_t)__cvta_generic_to_shared(sm);
    const uint32_t psB = sb + PS_OFF;
    float* l_smem = (float*)((char*)sm + L_OFF);

    const int lr7 = lane & 7, lb3 = (lane >> 3) & 1, lb4 = (lane >> 4) & 1;
    const uint32_t bK0 = sb + ((lr7 + lb4 * 8) * ALD + lb3 * 4) * 4;
    const uint32_t bV0 = bK0 + 64 * ALD * 4;
    uint32_t aP0[2];
#pragma unroll
    for (int i = 0; i < 2; i++)
        aP0[i] = psB + ((wrow + i * 16 + lr7 + lb3 * 8) * ALD + lb4 * 4) * 4;

    const int wg_tid = tid & 127;
    const int r8  = wg_tid >> 4, q16 = wg_tid & 15;

    {
        const int rq = tid >> 4, qq = tid & 15;
#pragma unroll
        for (int i = 0; i < 8; i++) {
            const int rr = rq + i * 16;
            CPA(psB + (rr * ALD + qq * 4) * 4, Qg + rr * DH + qq * 4);
        }
        CPC();
    }
    if (isS) {
#pragma unroll
        for (int i = 0; i < 8; i++) {
            const int rr = r8 + i * 8;
            CPA(sb + (rr * ALD + q16 * 4) * 4, Kg + rr * DH + q16 * 4);
        }
        CPC();
    } else {
#pragma unroll
        for (int i = 0; i < 8; i++) {
            const int rr = r8 + i * 8;
            CPA(sb + 64 * ALD * 4 + (rr * ALD + q16 * 4) * 4,
                Vg + (size_t)rr * SEQ + q16 * 4);
        }
        CPC();
    }
    CPW(1);
    __syncthreads();

    if (isS) {
        unsigned Qf[2][8][4];
#pragma unroll
        for (int i = 0; i < 2; i++)
#pragma unroll
            for (int kk = 0; kk < 8; kk++) ldsm4(Qf[i][kk], aP0[i] + kk * 32);

        float lA[2] = {0.f, 0.f}, lB[2] = {0.f, 0.f};
        unsigned* Ps = sm + PS_OFF / 4;

        for (int kt = 0; kt < SEQ / 64; kt++) {
            const uint32_t cu = (uint32_t)(kt & 1) * KVSTRIDE;
            CPW(0);
            BAR_SYNC(9, 128);
            if (kt < SEQ / 64 - 1) {
                const uint32_t nb = (uint32_t)((kt + 1) & 1) * KVSTRIDE;
                const float* Kt = Kg + (size_t)(kt + 1) * 64 * DH;
#pragma unroll
                for (int i = 0; i < 8; i++) {
                    const int rr = r8 + i * 8;
                    CPA(sb + nb + (rr * ALD + q16 * 4) * 4, Kt + rr * DH + q16 * 4);
                }
                CPC();
            }

#pragma unroll
            for (int hf = 0; hf < 2; hf++) {
                float s[2][4][4];
#pragma unroll
                for (int i = 0; i < 2; i++)
#pragma unroll
                    for (int j = 0; j < 4; j++)
#pragma unroll
                        for (int r = 0; r < 4; r++) s[i][j][r] = 0.f;
#pragma unroll
                for (int kk = 0; kk < 8; kk++) {
#pragma unroll
                    for (int jl = 0; jl < 2; jl++) {
                        unsigned bk[4];
                        ldsm4(bk, bK0 + cu + (2*hf + jl) * (16 * ALD * 4) + kk * 32);
#pragma unroll
                        for (int i = 0; i < 2; i++) {
                            mma8(s[i][2*jl],     Qf[i][kk], bk);
                            mma8(s[i][2*jl + 1], Qf[i][kk], bk + 2);
                        }
                    }
                }
#pragma unroll
                for (int i = 0; i < 2; i++)
#pragma unroll
                    for (int j = 0; j < 4; j++) {
                        s[i][j][0] = ex2(s[i][j][0]);
                        s[i][j][1] = ex2(s[i][j][1]);
                        s[i][j][2] = ex2(s[i][j][2]);
                        s[i][j][3] = ex2(s[i][j][3]);
                        lA[i] += s[i][j][0] + s[i][j][1];
                        lB[i] += s[i][j][2] + s[i][j][3];
                    }
                if (hf == 0) BAR_SYNC_R(idFree, 64);
#pragma unroll
                for (int i = 0; i < 2; i++)
#pragma unroll
                    for (int j = 0; j < 4; j++) {
                        const int col = (4*hf + j) * 8 + 2 * t4;
                        uint2 u0, u1;
                        u0.x = f2tf(s[i][j][0]); u0.y = f2tf(s[i][j][1]);
                        u1.x = f2tf(s[i][j][2]); u1.y = f2tf(s[i][j][3]);
                        *(uint2*)&Ps[(wrow + i*16 + g)     * ALD + col] = u0;
                        *(uint2*)&Ps[(wrow + i*16 + g + 8) * ALD + col] = u1;
                    }
            }
            BAR_ARRIVE_R(idReady, 64);
        }

#pragma unroll
        for (int i = 0; i < 2; i++) {
            lA[i] += __shfl_xor_sync(0xffffffffu, lA[i], 1);
            lA[i] += __shfl_xor_sync(0xffffffffu, lA[i], 2);
            lB[i] += __shfl_xor_sync(0xffffffffu, lB[i], 1);
            lB[i] += __shfl_xor_sync(0xffffffffu, lB[i], 2);
            if (t4 == 0) {
                l_smem[wrow + i*16 + g]     = lA[i];
                l_smem[wrow + i*16 + g + 8] = lB[i];
            }
        }
        __syncthreads();
    } else {
        float o[2][8][4];
#pragma unroll
        for (int i = 0; i < 2; i++)
#pragma unroll
            for (int j = 0; j < 8; j++)
#pragma unroll
                for (int r = 0; r < 4; r++) o[i][j][r] = 0.f;

        BAR_ARRIVE_R(idFree, 64);

        for (int kt = 0; kt < SEQ / 64; kt++) {
            const uint32_t cu = (uint32_t)(kt & 1) * KVSTRIDE;
            CPW(0);
            BAR_SYNC(10, 128);
            if (kt < SEQ / 64 - 1) {
                const uint32_t nb = (uint32_t)((kt + 1) & 1) * KVSTRIDE;
                const float* Vt = Vg + (kt + 1) * 64;
#pragma unroll
                for (int i = 0; i < 8; i++) {
                    const int rr = r8 + i * 8;
                    CPA(sb + nb + 64 * ALD * 4 + (rr * ALD + q16 * 4) * 4,
                        Vt + (size_t)rr * SEQ + q16 * 4);
                }
                CPC();
            }
            BAR_SYNC_R(idReady, 64);

#pragma unroll
            for (int kc = 0; kc < 8; kc++) {
                unsigned ap[2][4];
                ldsm4(ap[0], aP0[0] + kc * 32);
                ldsm4(ap[1], aP0[1] + kc * 32);
#pragma unroll
                for (int jj = 0; jj < 4; jj++) {
                    unsigned bv[4];
                    ldsm4(bv, bV0 + cu + jj * (16 * ALD * 4) + kc * 32);
#pragma unroll
                    for (int i = 0; i < 2; i++) {
                        mma8(o[i][2 * jj],     ap[i], bv);
                        mma8(o[i][2 * jj + 1], ap[i], bv + 2);
                    }
                }
            }
            BAR_ARRIVE_R(idFree, 64);
        }

        __syncthreads();

#pragma unroll
        for (int i = 0; i < 2; i++) {
            const float invA = 1.f / l_smem[wrow + i*16 + g];
            const float invB = 1.f / l_smem[wrow + i*16 + g + 8];
            const int rA = qt * 128 + wrow + i * 16 + g;
            float* oA = out + ((size_t)(b * SEQ + rA)) * DM + h * DH;
            float* oB = oA + (size_t)8 * DM;
#pragma unroll
            for (int j = 0; j < 8; j++) {
                const int col = j * 8 + 2 * t4;
                float2 vA, vB;
                vA.x = rtf(o[i][j][0] * invA); vA.y = rtf(o[i][j][1] * invA);
                vB.x = rtf(o[i][j][2] * invB); vB.y = rtf(o[i][j][3] * invB);
                *(float2*)(oA + col) = vA;
                *(float2*)(oB + col) = vB;
            }
        }
    }
}

// ---------------------------------------------------------------------------
extern "C" void kernel_launch(void* const* d_in, const int* in_sizes, int n_in,
                              void* d_out, int out_size)
{
    const float* x  = (const float*)d_in[0];
    const float* Wq = (const float*)d_in[1];
    const float* bq = (const float*)d_in[2];
    const float* Wk = (const float*)d_in[3];
    const float* bk = (const float*)d_in[4];
    const float* Wv = (const float*)d_in[5];
    const float* bv = (const float*)d_in[6];
    const float* Wo = (const float*)d_in[7];
    const float* bo = (const float*)d_in[8];
    float* out = (float*)d_out;

    float *xr, *wr_, *q, *k, *vt, *att;
    cudaGetSymbolAddress((void**)&xr,  g_x);
    cudaGetSymbolAddress((void**)&wr_, g_w);
    cudaGetSymbolAddress((void**)&q,   g_q);
    cudaGetSymbolAddress((void**)&k,   g_k);
    cudaGetSymbolAddress((void**)&vt,  g_vt);
    cudaGetSymbolAddress((void**)&att, g_att);

    cudaFuncSetAttribute(qkv_mma,
        cudaFuncAttributeMaxDynamicSharedMemorySize, QKV_SMEM);
    cudaFuncSetAttribute(o_mma,
        cudaFuncAttributeMaxDynamicSharedMemorySize, O_SMEM);
    cudaFuncSetAttribute(attn_mma,
        cudaFuncAttributeMaxDynamicSharedMemorySize, ATT_SMEM_BYTES);

    const int XN4 = NTOK * DM / 4;
    const int WN4 = DM * DM / 4;

    prep_all<<<dim3(XN4 / 256, 5), 256>>>(x, Wq, Wk, Wv, Wo, xr, wr_, XN4, WN4);

    qkv_mma<<<dim3(12, NTOK / PBM), 256, QKV_SMEM>>>(
        xr, wr_, bq, bk, bv, q, k, vt);

    attn_mma<<<dim3(SEQ / 128, NH, BAT), 256, ATT_SMEM_BYTES>>>(q, k, vt, att);

    o_mma<<<dim3(8, NTOK / PBM), 256, O_SMEM>>>(att, wr_ + 3*DM*DM, bo, out);
}

// round 16
// speedup vs baseline: 1.0337x; 1.0102x over previous
#include <cuda_runtime.h>
#include <math.h>
#include <stdint.h>

#define DM   512
#define NH   8
#define DH   64
#define BAT  2
#define SEQ  2048
#define NTOK (BAT*SEQ)   // 4096

// Scratch (device globals)
__device__ float g_x[NTOK*DM];           // x pre-rounded to tf32
__device__ float g_w[4*DM*DM];           // Wq,Wk,Wv,Wo pre-rounded to tf32
__device__ float g_q[BAT*NH*SEQ*DH];     // [B,H,S,d], scaled by log2(e)/8, tf32
__device__ float g_k[BAT*NH*SEQ*DH];     // [B,H,S,d], tf32
__device__ float g_vt[BAT*NH*DH*SEQ];    // V TRANSPOSED [B,H,d,S], tf32
__device__ float g_att[NTOK*DM];         // attention output [B,S,D], tf32

// ---------------------------------------------------------------------------
// helpers
// ---------------------------------------------------------------------------
__device__ __forceinline__ unsigned f2tf(float f) {
    unsigned u;
    asm("cvt.rna.tf32.f32 %0, %1;" : "=r"(u) : "f"(f));
    return u;
}
__device__ __forceinline__ float rtf(float f) { return __uint_as_float(f2tf(f)); }
__device__ __forceinline__ float ex2(float f) {
    float r;
    asm("ex2.approx.f32 %0, %1;" : "=f"(r) : "f"(f));
    return r;
}

__device__ __forceinline__ void mma8(float* c, const unsigned* a, const unsigned* b) {
    asm volatile(
        "mma.sync.aligned.m16n8k8.row.col.f32.tf32.tf32.f32 "
        "{%0,%1,%2,%3}, {%4,%5,%6,%7}, {%8,%9}, {%0,%1,%2,%3};"
        : "+f"(c[0]), "+f"(c[1]), "+f"(c[2]), "+f"(c[3])
        : "r"(a[0]), "r"(a[1]), "r"(a[2]), "r"(a[3]), "r"(b[0]), "r"(b[1]));
}

__device__ __forceinline__ void ldsm4(unsigned* r, uint32_t addr) {
    asm volatile("ldmatrix.sync.aligned.m8n8.x4.shared.b16 {%0,%1,%2,%3}, [%4];"
        : "=r"(r[0]), "=r"(r[1]), "=r"(r[2]), "=r"(r[3]) : "r"(addr));
}

#define CPA(dst, src) \
    asm volatile("cp.async.cg.shared.global [%0], [%1], 16;" :: "r"(dst), "l"(src))
#define CPC() asm volatile("cp.async.commit_group;" ::: "memory")
#define CPW(n) asm volatile("cp.async.wait_group %0;" :: "n"(n) : "memory")

#define BAR_SYNC(id, cnt) \
    asm volatile("bar.sync %0, %1;" :: "n"(id), "n"(cnt) : "memory")
#define BAR_SYNC_R(id, cnt) \
    asm volatile("bar.sync %0, %1;" :: "r"(id), "n"(cnt) : "memory")
#define BAR_ARRIVE_R(id, cnt) \
    asm volatile("bar.arrive %0, %1;" :: "r"(id), "n"(cnt) : "memory")

// ---------------------------------------------------------------------------
// prep: RNA-round fp32 -> tf32 for x (y=0) and W[0..3] (y=1..4), one launch
// ---------------------------------------------------------------------------
__global__ __launch_bounds__(256)
void prep_all(const float* __restrict__ x,
              const float* __restrict__ w0, const float* __restrict__ w1,
              const float* __restrict__ w2, const float* __restrict__ w3,
              float* __restrict__ xr, float* __restrict__ wrd,
              int xn4, int wn4)
{
    const int y = blockIdx.y;
    const int i = blockIdx.x * 256 + threadIdx.x;
    const float* src;
    float* dst;
    int n4;
    if (y == 0) { src = x; dst = xr; n4 = xn4; }
    else {
        src = (y == 1) ? w0 : (y == 2) ? w1 : (y == 3) ? w2 : w3;
        dst = wrd + (size_t)(y - 1) * DM * DM;
        n4 = wn4;
    }
    if (i < n4) {
        float4 v = ((const float4*)src)[i];
        v.x = rtf(v.x); v.y = rtf(v.y); v.z = rtf(v.z); v.w = rtf(v.w);
        ((float4*)dst)[i] = v;
    }
}

// ---------------------------------------------------------------------------
// Fused QKV projection (inputs pre-rounded tf32) — unchanged from R15.
// CTA tile 128x128, grid (12, 32); K-chunk 32, double-buffered.
// Q epilogue scale = log2(e)/8 (for ex2 softmax).
// ---------------------------------------------------------------------------
#define PBM 128
#define PBK 32
#define PLD 36
#define TLD 132
#define QKV_BUFW ((PBM + 128) * PLD)
#define QKV_SMEM (2 * QKV_BUFW * 4)
#define QSCALE 0.18033688011112042f   // log2(e) / 8

__global__ __launch_bounds__(256, 2)
void qkv_mma(const float* __restrict__ A, const float* __restrict__ W4,
             const float* __restrict__ bq, const float* __restrict__ bk,
             const float* __restrict__ bv,
             float* __restrict__ outq, float* __restrict__ outk,
             float* __restrict__ outvt)
{
    extern __shared__ unsigned psm[];

    const int tid  = threadIdx.x;
    const int lane = tid & 31;
    const int wid  = tid >> 5;
    const int wr   = wid >> 1;
    const int wc   = wid & 1;
    const int g    = lane >> 2;
    const int t4   = lane & 3;
    const int bm   = blockIdx.y;
    const int bnG  = blockIdx.x;
    const int mat  = bnG >> 2;
    const int nb   = bnG & 3;

    const float* Ag = A + (size_t)bm * PBM * DM;
    const float* Wg = W4 + (size_t)mat * DM * DM + (size_t)nb * 128 * DM;
    const float* bias = (mat == 0) ? bq : (mat == 1) ? bk : bv;

    const uint32_t sb   = (uint32_t)__cvta_generic_to_shared(psm);
    const uint32_t BUFB = QKV_BUFW * 4;
    const uint32_t bOff = PBM * PLD * 4;

    const int lr7 = lane & 7, lb3 = (lane >> 3) & 1, lb4 = (lane >> 4) & 1;
    uint32_t aAddr[2], bAddr[4];
#pragma unroll
    for (int i = 0; i < 2; i++)
        aAddr[i] = sb + ((wr*32 + i*16 + lr7 + lb3*8) * PLD + lb4*4) * 4;
#pragma unroll
    for (int jj = 0; jj < 4; jj++)
        bAddr[jj] = sb + bOff + ((wc*64 + jj*16 + lr7 + lb4*8) * PLD + lb3*4) * 4;

    const int cr = tid >> 3, cq = tid & 7;

#pragma unroll
    for (int i = 0; i < 4; i++) {
        const int r = cr + i * 32;
        CPA(sb + (r*PLD + cq*4)*4, Ag + (size_t)r * DM + cq*4);
        CPA(sb + bOff + (r*PLD + cq*4)*4, Wg + (size_t)r * DM + cq*4);
    }
    CPC();

    float acc[2][8][4];
#pragma unroll
    for (int i = 0; i < 2; i++)
#pragma unroll
        for (int j = 0; j < 8; j++)
#pragma unroll
            for (int r = 0; r < 4; r++) acc[i][j][r] = 0.f;

    for (int c = 0; c < DM / PBK; c++) {
        const uint32_t cu = (c & 1) * BUFB;
        CPW(0);
        __syncthreads();
        if (c < DM / PBK - 1) {
            const uint32_t nbuf = ((c + 1) & 1) * BUFB;
            const int k0 = (c + 1) * PBK;
#pragma unroll
            for (int i = 0; i < 4; i++) {
                const int r = cr + i * 32;
                CPA(sb + nbuf + (r*PLD + cq*4)*4, Ag + (size_t)r * DM + k0 + cq*4);
                CPA(sb + nbuf + bOff + (r*PLD + cq*4)*4, Wg + (size_t)r * DM + k0 + cq*4);
            }
            CPC();
        }
#pragma unroll
        for (int kk = 0; kk < PBK / 8; kk++) {
            unsigned af[2][4], bf[4][4];
            ldsm4(af[0], aAddr[0] + cu + kk * 32);
            ldsm4(af[1], aAddr[1] + cu + kk * 32);
#pragma unroll
            for (int jj = 0; jj < 4; jj++)
                ldsm4(bf[jj], bAddr[jj] + cu + kk * 32);
#pragma unroll
            for (int i = 0; i < 2; i++)
#pragma unroll
                for (int j = 0; j < 8; j++)
                    mma8(acc[i][j], af[i], bf[j >> 1] + (j & 1) * 2);
        }
    }

    if (mat == 2) {
        float* Ts = (float*)psm;
        __syncthreads();
#pragma unroll
        for (int i = 0; i < 2; i++) {
            const int ss = wr*32 + i*16 + g;
#pragma unroll
            for (int j = 0; j < 8; j++) {
                const int cc = wc*64 + j*8 + 2*t4;
                const float b0 = bias[nb*128 + cc], b1 = bias[nb*128 + cc + 1];
                Ts[cc * TLD + ss]           = rtf(acc[i][j][0] + b0);
                Ts[(cc + 1) * TLD + ss]     = rtf(acc[i][j][1] + b1);
                Ts[cc * TLD + ss + 8]       = rtf(acc[i][j][2] + b0);
                Ts[(cc + 1) * TLD + ss + 8] = rtf(acc[i][j][3] + b1);
            }
        }
        __syncthreads();
        const int bb = bm >> 4;
        const int sbase = (bm & 15) * 128;
#pragma unroll
        for (int t = 0; t < 16; t++) {
            const int idx = tid + t * 256;
            const int cc = idx >> 5;
            const int sl = (idx & 31) * 4;
            const int mc = nb * 128 + cc;
            const int hh = mc >> 6, dd = mc & (DH - 1);
            float4 val = *(float4*)&Ts[cc * TLD + sl];
            *(float4*)(outvt + (((size_t)bb * NH + hh) * DH + dd) * SEQ + sbase + sl) = val;
        }
        return;
    }

    float* out = mat ? outk : outq;
    const float scale = mat ? 1.0f : QSCALE;
#pragma unroll
    for (int i = 0; i < 2; i++) {
        const int row0 = bm * PBM + wr * 32 + i * 16 + g;
        const int row1 = row0 + 8;
        const int b0 = row0 >> 11, s0 = row0 & (SEQ - 1);
        const int b1 = row1 >> 11, s1 = row1 & (SEQ - 1);
#pragma unroll
        for (int j = 0; j < 8; j++) {
            const int col0 = nb * 128 + wc * 64 + j * 8 + 2 * t4;
            const int hh = col0 >> 6, cc = col0 & (DH - 1);
            float* p0 = &out[(((size_t)b0 * NH + hh) * SEQ + s0) * DH + cc];
            p0[0] = rtf((acc[i][j][0] + bias[col0])     * scale);
            p0[1] = rtf((acc[i][j][1] + bias[col0 + 1]) * scale);
            float* p1 = &out[(((size_t)b1 * NH + hh) * SEQ + s1) * DH + cc];
            p1[0] = rtf((acc[i][j][2] + bias[col0])     * scale);
            p1[1] = rtf((acc[i][j][3] + bias[col0 + 1]) * scale);
        }
    }
}

// ---------------------------------------------------------------------------
// O projection, K-CHUNK 64 (8 chunks): halves barrier bubbles, doubles ILP.
// CTA tile 128x64, grid (8, 32). 2-stage double buffer, 2 CTAs/SM.
// Buffer: A 128x64 + B 64x64 tf32, leading dim 68.
// ---------------------------------------------------------------------------
#define OK   64                              // K-chunk
#define OLD  68                              // leading dim (68 % 32 == 4)
#define O_BUFW ((128 + 64) * OLD)            // 13056 words per stage
#define O_SMEM (2 * O_BUFW * 4)              // 104448 B

__global__ __launch_bounds__(256, 2)
void o_mma(const float* __restrict__ A, const float* __restrict__ W,
           const float* __restrict__ bias, float* __restrict__ out)
{
    extern __shared__ unsigned psm[];

    const int tid  = threadIdx.x;
    const int lane = tid & 31;
    const int wid  = tid >> 5;
    const int wr   = wid >> 1;
    const int wc   = wid & 1;
    const int g    = lane >> 2;
    const int t4   = lane & 3;
    const int bm   = blockIdx.y;
    const int bn   = blockIdx.x;

    const float* Ag = A + (size_t)bm * PBM * DM;
    const float* Wg = W + (size_t)bn * 64 * DM;

    const uint32_t sb   = (uint32_t)__cvta_generic_to_shared(psm);
    const uint32_t BUFB = O_BUFW * 4;
    const uint32_t bOff = 128 * OLD * 4;     // B region offset

    const int lr7 = lane & 7, lb3 = (lane >> 3) & 1, lb4 = (lane >> 4) & 1;
    uint32_t aAddr[2], bAddr[2];
#pragma unroll
    for (int i = 0; i < 2; i++)
        aAddr[i] = sb + ((wr*32 + i*16 + lr7 + lb3*8) * OLD + lb4*4) * 4;
#pragma unroll
    for (int jj = 0; jj < 2; jj++)
        bAddr[jj] = sb + bOff + ((wc*32 + jj*16 + lr7 + lb4*8) * OLD + lb3*4) * 4;

    // copy: rows have 16 float4s. cr16 = tid>>4 (0..15), cq16 = tid&15.
    const int cr16 = tid >> 4, cq16 = tid & 15;

    // prologue: chunk 0 -> buf 0
#pragma unroll
    for (int i = 0; i < 8; i++) {
        const int r = cr16 + i * 16;
        CPA(sb + (r*OLD + cq16*4)*4, Ag + (size_t)r * DM + cq16*4);
    }
#pragma unroll
    for (int i = 0; i < 4; i++) {
        const int r = cr16 + i * 16;
        CPA(sb + bOff + (r*OLD + cq16*4)*4, Wg + (size_t)r * DM + cq16*4);
    }
    CPC();

    float acc[2][4][4];
#pragma unroll
    for (int i = 0; i < 2; i++)
#pragma unroll
        for (int j = 0; j < 4; j++)
#pragma unroll
            for (int r = 0; r < 4; r++) acc[i][j][r] = 0.f;

    for (int c = 0; c < DM / OK; c++) {      // 8 chunks
        const uint32_t cu = (c & 1) * BUFB;
        CPW(0);
        __syncthreads();
        if (c < DM / OK - 1) {
            const uint32_t nbuf = ((c + 1) & 1) * BUFB;
            const int k0 = (c + 1) * OK;
#pragma unroll
            for (int i = 0; i < 8; i++) {
                const int r = cr16 + i * 16;
                CPA(sb + nbuf + (r*OLD + cq16*4)*4, Ag + (size_t)r * DM + k0 + cq16*4);
            }
#pragma unroll
            for (int i = 0; i < 4; i++) {
                const int r = cr16 + i * 16;
                CPA(sb + nbuf + bOff + (r*OLD + cq16*4)*4, Wg + (size_t)r * DM + k0 + cq16*4);
            }
            CPC();
        }
#pragma unroll
        for (int kk = 0; kk < OK / 8; kk++) {    // 8 k-steps
            unsigned af[2][4], bf[2][4];
            ldsm4(af[0], aAddr[0] + cu + kk * 32);
            ldsm4(af[1], aAddr[1] + cu + kk * 32);
            ldsm4(bf[0], bAddr[0] + cu + kk * 32);
            ldsm4(bf[1], bAddr[1] + cu + kk * 32);
#pragma unroll
            for (int i = 0; i < 2; i++) {
                mma8(acc[i][0], af[i], bf[0]);
                mma8(acc[i][1], af[i], bf[0] + 2);
                mma8(acc[i][2], af[i], bf[1]);
                mma8(acc[i][3], af[i], bf[1] + 2);
            }
        }
    }

#pragma unroll
    for (int i = 0; i < 2; i++) {
        const int row0 = bm * PBM + wr * 32 + i * 16 + g;
        const int row1 = row0 + 8;
#pragma unroll
        for (int j = 0; j < 4; j++) {
            const int col0 = bn * 64 + wc * 32 + j * 8 + 2 * t4;
            float* p0 = &out[(size_t)row0 * DM + col0];
            p0[0] = acc[i][j][0] + bias[col0];
            p0[1] = acc[i][j][1] + bias[col0 + 1];
            float* p1 = &out[(size_t)row1 * DM + col0];
            p1[0] = acc[i][j][2] + bias[col0];
            p1[1] = acc[i][j][3] + bias[col0 + 1];
        }
    }
}

// ---------------------------------------------------------------------------
// Flash attention (unchanged from R15): warp-specialized, pairwise P handoff,
// ex2 softmax with pre-scaled Q.
// ---------------------------------------------------------------------------
#define ALD 68
#define KVSTRIDE (2 * 64 * ALD * 4)
#define PS_OFF   (2 * KVSTRIDE)
#define L_OFF    (PS_OFF + 128 * ALD * 4)
#define ATT_SMEM_BYTES (L_OFF + 512)

__global__ __launch_bounds__(256, 2)
void attn_mma(const float* __restrict__ Q, const float* __restrict__ K,
              const float* __restrict__ VT, float* __restrict__ out)
{
    extern __shared__ unsigned sm[];

    const int tid  = threadIdx.x;
    const int lane = tid & 31;
    const int wid  = tid >> 5;
    const bool isS = wid < 4;
    const int wg   = wid & 3;
    const int wrow = wg * 32;
    const int g    = lane >> 2;
    const int t4   = lane & 3;
    const int qt   = blockIdx.x;
    const int h    = blockIdx.y;
    const int b    = blockIdx.z;

    const int idReady = 1 + wg;
    const int idFree  = 5 + wg;

    const float* Qg = Q  + (((size_t)b * NH + h) * SEQ + qt * 128) * DH;
    const float* Kg = K  + ((size_t)b * NH + h) * SEQ * DH;
    const float* Vg = VT + ((size_t)b * NH + h) * DH * SEQ;

    const uint32_t sb  = (uint32_t)__cvta_generic_to_shared(sm);
    const uint32_t psB = sb + PS_OFF;
    float* l_smem = (float*)((char*)sm + L_OFF);

    const int lr7 = lane & 7, lb3 = (lane >> 3) & 1, lb4 = (lane >> 4) & 1;
    const uint32_t bK0 = sb + ((lr7 + lb4 * 8) * ALD + lb3 * 4) * 4;
    const uint32_t bV0 = bK0 + 64 * ALD * 4;
    uint32_t aP0[2];
#pragma unroll
    for (int i = 0; i < 2; i++)
        aP0[i] = psB + ((wrow + i * 16 + lr7 + lb3 * 8) * ALD + lb4 * 4) * 4;

    const int wg_tid = tid & 127;
    const int r8  = wg_tid >> 4, q16 = wg_tid & 15;

    {
        const int rq = tid >> 4, qq = tid & 15;
#pragma unroll
        for (int i = 0; i < 8; i++) {
            const int rr = rq + i * 16;
            CPA(psB + (rr * ALD + qq * 4) * 4, Qg + rr * DH + qq * 4);
        }
        CPC();
    }
    if (isS) {
#pragma unroll
        for (int i = 0; i < 8; i++) {
            const int rr = r8 + i * 8;
            CPA(sb + (rr * ALD + q16 * 4) * 4, Kg + rr * DH + q16 * 4);
        }
        CPC();
    } else {
#pragma unroll
        for (int i = 0; i < 8; i++) {
            const int rr = r8 + i * 8;
            CPA(sb + 64 * ALD * 4 + (rr * ALD + q16 * 4) * 4,
                Vg + (size_t)rr * SEQ + q16 * 4);
        }
        CPC();
    }
    CPW(1);
    __syncthreads();

    if (isS) {
        unsigned Qf[2][8][4];
#pragma unroll
        for (int i = 0; i < 2; i++)
#pragma unroll
            for (int kk = 0; kk < 8; kk++) ldsm4(Qf[i][kk], aP0[i] + kk * 32);

        float lA[2] = {0.f, 0.f}, lB[2] = {0.f, 0.f};
        unsigned* Ps = sm + PS_OFF / 4;

        for (int kt = 0; kt < SEQ / 64; kt++) {
            const uint32_t cu = (uint32_t)(kt & 1) * KVSTRIDE;
            CPW(0);
            BAR_SYNC(9, 128);
            if (kt < SEQ / 64 - 1) {
                const uint32_t nb = (uint32_t)((kt + 1) & 1) * KVSTRIDE;
                const float* Kt = Kg + (size_t)(kt + 1) * 64 * DH;
#pragma unroll
                for (int i = 0; i < 8; i++) {
                    const int rr = r8 + i * 8;
                    CPA(sb + nb + (rr * ALD + q16 * 4) * 4, Kt + rr * DH + q16 * 4);
                }
                CPC();
            }

#pragma unroll
            for (int hf = 0; hf < 2; hf++) {
                float s[2][4][4];
#pragma unroll
                for (int i = 0; i < 2; i++)
#pragma unroll
                    for (int j = 0; j < 4; j++)
#pragma unroll
                        for (int r = 0; r < 4; r++) s[i][j][r] = 0.f;
#pragma unroll
                for (int kk = 0; kk < 8; kk++) {
#pragma unroll
                    for (int jl = 0; jl < 2; jl++) {
                        unsigned bk[4];
                        ldsm4(bk, bK0 + cu + (2*hf + jl) * (16 * ALD * 4) + kk * 32);
#pragma unroll
                        for (int i = 0; i < 2; i++) {
                            mma8(s[i][2*jl],     Qf[i][kk], bk);
                            mma8(s[i][2*jl + 1], Qf[i][kk], bk + 2);
                        }
                    }
                }
#pragma unroll
                for (int i = 0; i < 2; i++)
#pragma unroll
                    for (int j = 0; j < 4; j++) {
                        s[i][j][0] = ex2(s[i][j][0]);
                        s[i][j][1] = ex2(s[i][j][1]);
                        s[i][j][2] = ex2(s[i][j][2]);
                        s[i][j][3] = ex2(s[i][j][3]);
                        lA[i] += s[i][j][0] + s[i][j][1];
                        lB[i] += s[i][j][2] + s[i][j][3];
                    }
                if (hf == 0) BAR_SYNC_R(idFree, 64);
#pragma unroll
                for (int i = 0; i < 2; i++)
#pragma unroll
                    for (int j = 0; j < 4; j++) {
                        const int col = (4*hf + j) * 8 + 2 * t4;
                        uint2 u0, u1;
                        u0.x = f2tf(s[i][j][0]); u0.y = f2tf(s[i][j][1]);
                        u1.x = f2tf(s[i][j][2]); u1.y = f2tf(s[i][j][3]);
                        *(uint2*)&Ps[(wrow + i*16 + g)     * ALD + col] = u0;
                        *(uint2*)&Ps[(wrow + i*16 + g + 8) * ALD + col] = u1;
                    }
            }
            BAR_ARRIVE_R(idReady, 64);
        }

#pragma unroll
        for (int i = 0; i < 2; i++) {
            lA[i] += __shfl_xor_sync(0xffffffffu, lA[i], 1);
            lA[i] += __shfl_xor_sync(0xffffffffu, lA[i], 2);
            lB[i] += __shfl_xor_sync(0xffffffffu, lB[i], 1);
            lB[i] += __shfl_xor_sync(0xffffffffu, lB[i], 2);
            if (t4 == 0) {
                l_smem[wrow + i*16 + g]     = lA[i];
                l_smem[wrow + i*16 + g + 8] = lB[i];
            }
        }
        __syncthreads();
    } else {
        float o[2][8][4];
#pragma unroll
        for (int i = 0; i < 2; i++)
#pragma unroll
            for (int j = 0; j < 8; j++)
#pragma unroll
                for (int r = 0; r < 4; r++) o[i][j][r] = 0.f;

        BAR_ARRIVE_R(idFree, 64);

        for (int kt = 0; kt < SEQ / 64; kt++) {
            const uint32_t cu = (uint32_t)(kt & 1) * KVSTRIDE;
            CPW(0);
            BAR_SYNC(10, 128);
            if (kt < SEQ / 64 - 1) {
                const uint32_t nb = (uint32_t)((kt + 1) & 1) * KVSTRIDE;
                const float* Vt = Vg + (kt + 1) * 64;
#pragma unroll
                for (int i = 0; i < 8; i++) {
                    const int rr = r8 + i * 8;
                    CPA(sb + nb + 64 * ALD * 4 + (rr * ALD + q16 * 4) * 4,
                        Vt + (size_t)rr * SEQ + q16 * 4);
                }
                CPC();
            }
            BAR_SYNC_R(idReady, 64);

#pragma unroll
            for (int kc = 0; kc < 8; kc++) {
                unsigned ap[2][4];
                ldsm4(ap[0], aP0[0] + kc * 32);
                ldsm4(ap[1], aP0[1] + kc * 32);
#pragma unroll
                for (int jj = 0; jj < 4; jj++) {
                    unsigned bv[4];
                    ldsm4(bv, bV0 + cu + jj * (16 * ALD * 4) + kc * 32);
#pragma unroll
                    for (int i = 0; i < 2; i++) {
                        mma8(o[i][2 * jj],     ap[i], bv);
                        mma8(o[i][2 * jj + 1], ap[i], bv + 2);
                    }
                }
            }
            BAR_ARRIVE_R(idFree, 64);
        }

        __syncthreads();

#pragma unroll
        for (int i = 0; i < 2; i++) {
            const float invA = 1.f / l_smem[wrow + i*16 + g];
            const float invB = 1.f / l_smem[wrow + i*16 + g + 8];
            const int rA = qt * 128 + wrow + i * 16 + g;
            float* oA = out + ((size_t)(b * SEQ + rA)) * DM + h * DH;
            float* oB = oA + (size_t)8 * DM;
#pragma unroll
            for (int j = 0; j < 8; j++) {
                const int col = j * 8 + 2 * t4;
                float2 vA, vB;
                vA.x = rtf(o[i][j][0] * invA); vA.y = rtf(o[i][j][1] * invA);
                vB.x = rtf(o[i][j][2] * invB); vB.y = rtf(o[i][j][3] * invB);
                *(float2*)(oA + col) = vA;
                *(float2*)(oB + col) = vB;
            }
        }
    }
}

// ---------------------------------------------------------------------------
extern "C" void kernel_launch(void* const* d_in, const int* in_sizes, int n_in,
                              void* d_out, int out_size)
{
    const float* x  = (const float*)d_in[0];
    const float* Wq = (const float*)d_in[1];
    const float* bq = (const float*)d_in[2];
    const float* Wk = (const float*)d_in[3];
    const float* bk = (const float*)d_in[4];
    const float* Wv = (const float*)d_in[5];
    const float* bv = (const float*)d_in[6];
    const float* Wo = (const float*)d_in[7];
    const float* bo = (const float*)d_in[8];
    float* out = (float*)d_out;

    float *xr, *wr_, *q, *k, *vt, *att;
    cudaGetSymbolAddress((void**)&xr,  g_x);
    cudaGetSymbolAddress((void**)&wr_, g_w);
    cudaGetSymbolAddress((void**)&q,   g_q);
    cudaGetSymbolAddress((void**)&k,   g_k);
    cudaGetSymbolAddress((void**)&vt,  g_vt);
    cudaGetSymbolAddress((void**)&att, g_att);

    cudaFuncSetAttribute(qkv_mma,
        cudaFuncAttributeMaxDynamicSharedMemorySize, QKV_SMEM);
    cudaFuncSetAttribute(o_mma,
        cudaFuncAttributeMaxDynamicSharedMemorySize, O_SMEM);
    cudaFuncSetAttribute(attn_mma,
        cudaFuncAttributeMaxDynamicSharedMemorySize, ATT_SMEM_BYTES);

    const int XN4 = NTOK * DM / 4;
    const int WN4 = DM * DM / 4;

    prep_all<<<dim3(XN4 / 256, 5), 256>>>(x, Wq, Wk, Wv, Wo, xr, wr_, XN4, WN4);

    qkv_mma<<<dim3(12, NTOK / PBM), 256, QKV_SMEM>>>(
        xr, wr_, bq, bk, bv, q, k, vt);

    attn_mma<<<dim3(SEQ / 128, NH, BAT), 256, ATT_SMEM_BYTES>>>(q, k, vt, att);

    o_mma<<<dim3(8, NTOK / PBM), 256, O_SMEM>>>(att, wr_ + 3*DM*DM, bo, out);
}